// round 12
// baseline (speedup 1.0000x reference)
#include <cuda_runtime.h>

#define FIN 512
#define HID 16
#define CO  7
#define NMAX 200000

// Scratch (no allocations allowed -> __device__ globals)
__device__ float g_deg [NMAX];
__device__ float g_dinv[NMAX];
__device__ float g_g1  [NMAX * HID];   // (x@W1) * dinv[row]
__device__ float g_t1  [NMAX * HID];   // scatter-add accumulator, layer 1
__device__ float g_g2  [NMAX * 8];     // (relu(out1)@W2) * dinv[row], padded to 8
__device__ float g_t2  [NMAX * 8];     // scatter-add accumulator, layer 2

typedef unsigned long long ull;

// ---------- helpers ----------
__device__ __forceinline__ void red4(float* p, float4 v) {
    asm volatile("red.global.add.v4.f32 [%0], {%1,%2,%3,%4};"
                 :: "l"(p), "f"(v.x), "f"(v.y), "f"(v.z), "f"(v.w) : "memory");
}
__device__ __forceinline__ void red1(float* p, float v) {
    asm volatile("red.global.add.f32 [%0], %1;" :: "l"(p), "f"(v) : "memory");
}
__device__ __forceinline__ ull fma2(ull a, ull b, ull c) {
    ull d;
    asm("fma.rn.f32x2 %0, %1, %2, %3;" : "=l"(d) : "l"(a), "l"(b), "l"(c));
    return d;
}
__device__ __forceinline__ ull pack2(float v) {
    ull r;
    asm("mov.b64 %0, {%1, %1};" : "=l"(r) : "f"(v));
    return r;
}
__device__ __forceinline__ float lo32(ull v) {
    return __uint_as_float((unsigned)(v & 0xffffffffull));
}
__device__ __forceinline__ float hi32(ull v) {
    return __uint_as_float((unsigned)(v >> 32));
}
__device__ __forceinline__ void mbar_init(unsigned a, int cnt) {
    asm volatile("mbarrier.init.shared.b64 [%0], %1;" :: "r"(a), "r"(cnt) : "memory");
}
__device__ __forceinline__ void mbar_expect(unsigned a, int tx) {
    asm volatile("mbarrier.arrive.expect_tx.shared.b64 _, [%0], %1;"
                 :: "r"(a), "r"(tx) : "memory");
}
__device__ __forceinline__ void mbar_wait(unsigned a, int ph) {
    asm volatile(
        "{\n\t.reg .pred P;\n\t"
        "W_%=:\n\t"
        "mbarrier.try_wait.parity.acquire.cta.shared::cta.b64 P, [%0], %1, 0x989680;\n\t"
        "@!P bra W_%=;\n\t}"
        :: "r"(a), "r"(ph) : "memory");
}
__device__ __forceinline__ void bulk_g2s(unsigned dst, const void* src, int bytes,
                                         unsigned mbar) {
    asm volatile("cp.async.bulk.shared::cta.global.mbarrier::complete_tx::bytes "
                 "[%0], [%1], %2, [%3];"
                 :: "r"(dst), "l"(src), "r"(bytes), "r"(mbar) : "memory");
}

// ---------- kernels ----------
// zero accumulators, deg = 1 (self loop)
__global__ void k_init(int n) {
    int i = blockIdx.x * blockDim.x + threadIdx.x;
    int total = n * HID;
    if (i < total)  g_t1[i] = 0.0f;
    if (i < n * 8)  g_t2[i] = 0.0f;
    if (i < n)      g_deg[i] = 1.0f;
}

__global__ void k_deg(const int* __restrict__ dst, int E) {
    int i = blockIdx.x * blockDim.x + threadIdx.x;
    if (i < E) red1(&g_deg[dst[i]], 1.0f);
}

__global__ void k_dinv(int n) {
    int i = blockIdx.x * blockDim.x + threadIdx.x;
    if (i < n) g_dinv[i] = rsqrtf(g_deg[i]);   // deg >= 1 always
}

// ---------------------------------------------------------------------------
// g1[row] = (x[row] @ W1) * dinv[row]
// 128 threads, 128 rows/CTA, 1 row/thread. x fed by the BULK-ASYNC engine:
// per 32-k tile each thread issues ONE cp.async.bulk of its row's 128-byte
// strip (full aligned line) into slot[row][36w] (144-B stride: 16B-aligned
// dst, (tid+m)%8 granule pattern -> conflict-free LDS.128). Ring of 4 slots,
// mbarrier+expect_tx per slot, refill depth 3. No LDGSTS issue-rate cap,
// no L1tex wavefront blowup. W1 in smem via broadcast LDS.128.
// ---------------------------------------------------------------------------
#define XB     128
#define KT     32               // k per tile
#define NT     (FIN / KT)       // 16 tiles
#define NSTG   4
#define SROW   36               // words per row in slot (32 + 4 pad)
#define SLOTW  (XB * SROW)      // 4608 words = 18432 B per slot
// smem layout (bytes): [0,128) mbarriers, [128, 128+32768) W1, then 4 slots
#define OFF_W    128
#define OFF_SLOT (OFF_W + FIN * HID * 4)
#define XSMEM    (OFF_SLOT + NSTG * SLOTW * 4)   // 106624 B

__global__ void __launch_bounds__(XB) k_xform(const float* __restrict__ x,
                                              const float* __restrict__ W1, int n) {
    extern __shared__ float smem[];
    const int tid = threadIdx.x;
    const int rowBase = blockIdx.x * XB;
    const int grow = rowBase + tid;
    const int srow = (grow < n) ? grow : (n - 1);    // clamp OOB reads

    unsigned sbase = (unsigned)__cvta_generic_to_shared(smem);
    unsigned mb    = sbase;                           // 4 mbarriers, 8B each
    unsigned myDst = sbase + OFF_SLOT + (unsigned)tid * (SROW * 4);

    // stage W1 (2048 float4, 16/thread)
    float4* Wst = (float4*)((char*)smem + OFF_W);
#pragma unroll
    for (int i = 0; i < 16; i++)
        Wst[i * XB + tid] = __ldg(&((const float4*)W1)[i * XB + tid]);
    const ulonglong2* W128 = (const ulonglong2*)((char*)smem + OFF_W);

    if (tid == 0)
#pragma unroll
        for (int s = 0; s < NSTG; s++) mbar_init(mb + 8 * s, 1);
    __syncthreads();   // mbarriers + W visible

    const float* xrow = x + (size_t)srow * FIN;

    // prologue: fill slots 0..3 with tiles 0..3
#pragma unroll
    for (int s = 0; s < NSTG; s++) {
        if (tid == 0) mbar_expect(mb + 8 * s, XB * 128);
        bulk_g2s(myDst + (unsigned)s * (SLOTW * 4), xrow + s * KT, 128, mb + 8 * s);
    }

    ull acc[8];
#pragma unroll
    for (int p = 0; p < 8; p++) acc[p] = 0ull;

    int ph = 0;
#pragma unroll 1
    for (int t = 0; t < NT; t++) {
        int s = t & (NSTG - 1);
        mbar_wait(mb + 8 * s, ph);
        if (s == NSTG - 1) ph ^= 1;

        const float4* Xr = (const float4*)(smem + OFF_SLOT / 4 + s * SLOTW + tid * SROW);
        int kt = t * KT;
#pragma unroll
        for (int m = 0; m < 8; m++) {
            float4 xq = Xr[m];                        // conflict-free LDS.128
            float xa[4];
            *(float4*)xa = xq;
#pragma unroll
            for (int c = 0; c < 4; c++) {
                int k = kt + 4 * m + c;
                ull x2 = pack2(xa[c]);
                ulonglong2 wA = W128[k * 4 + 0];
                ulonglong2 wB = W128[k * 4 + 1];
                ulonglong2 wC = W128[k * 4 + 2];
                ulonglong2 wD = W128[k * 4 + 3];
                acc[0] = fma2(x2, wA.x, acc[0]);
                acc[1] = fma2(x2, wA.y, acc[1]);
                acc[2] = fma2(x2, wB.x, acc[2]);
                acc[3] = fma2(x2, wB.y, acc[3]);
                acc[4] = fma2(x2, wC.x, acc[4]);
                acc[5] = fma2(x2, wC.y, acc[5]);
                acc[6] = fma2(x2, wD.x, acc[6]);
                acc[7] = fma2(x2, wD.y, acc[7]);
            }
        }

        __syncthreads();                              // slot s fully consumed
        if (t + NSTG < NT) {
            if (tid == 0) mbar_expect(mb + 8 * s, XB * 128);
            bulk_g2s(myDst + (unsigned)s * (SLOTW * 4),
                     xrow + (t + NSTG) * KT, 128, mb + 8 * s);
        }
    }

    if (grow < n) {
        float d = g_dinv[grow];
        float o[16];
#pragma unroll
        for (int p = 0; p < 8; p++) {
            o[2 * p]     = lo32(acc[p]) * d;
            o[2 * p + 1] = hi32(acc[p]) * d;
        }
        float4* dst4 = (float4*)&g_g1[(size_t)grow * HID];
#pragma unroll
        for (int v = 0; v < 4; v++) dst4[v] = *(float4*)&o[4 * v];
    }
}

// scatter-add g1[src] into t1[dst] — 4 threads per edge (16B each).
__global__ void k_agg1(const int* __restrict__ src, const int* __restrict__ dst, int E) {
    int i = blockIdx.x * blockDim.x + threadIdx.x;
    int e = i >> 2;
    if (e >= E) return;
    int j = i & 3;
    int s = src[e], d = dst[e];
    float4 v = __ldg((const float4*)&g_g1[(size_t)s * HID] + j);
    red4((float*)((float4*)&g_t1[(size_t)d * HID] + j), v);
}

// out1 = relu(dinv*(t1 + g1) + b1);  g2 = (out1 @ W2) * dinv
__global__ void k_mid(const float* __restrict__ W2, const float* __restrict__ b1, int n) {
    int i = blockIdx.x * blockDim.x + threadIdx.x;
    if (i >= n) return;
    float d = g_dinv[i];
    float h[16];
#pragma unroll
    for (int q = 0; q < 4; q++) {
        float4 tv = *(const float4*)&g_t1[(size_t)i * HID + 4 * q];
        float4 gv = *(const float4*)&g_g1[(size_t)i * HID + 4 * q];
        h[4 * q + 0] = fmaxf(d * (tv.x + gv.x) + __ldg(&b1[4 * q + 0]), 0.0f);
        h[4 * q + 1] = fmaxf(d * (tv.y + gv.y) + __ldg(&b1[4 * q + 1]), 0.0f);
        h[4 * q + 2] = fmaxf(d * (tv.z + gv.z) + __ldg(&b1[4 * q + 2]), 0.0f);
        h[4 * q + 3] = fmaxf(d * (tv.w + gv.w) + __ldg(&b1[4 * q + 3]), 0.0f);
    }
    float o[CO];
#pragma unroll
    for (int j = 0; j < CO; j++) o[j] = 0.0f;
#pragma unroll
    for (int k = 0; k < HID; k++)
#pragma unroll
        for (int j = 0; j < CO; j++)
            o[j] = fmaf(h[k], __ldg(&W2[k * CO + j]), o[j]);
    float out8[8];
#pragma unroll
    for (int j = 0; j < CO; j++) out8[j] = o[j] * d;
    out8[7] = 0.0f;
    float4* dst4 = (float4*)&g_g2[(size_t)i * 8];
    dst4[0] = *(float4*)&out8[0];
    dst4[1] = *(float4*)&out8[4];
}

// scatter-add g2[src] into t2[dst] — 2 threads per edge (16B each).
__global__ void k_agg2(const int* __restrict__ src, const int* __restrict__ dst, int E) {
    int i = blockIdx.x * blockDim.x + threadIdx.x;
    int e = i >> 1;
    if (e >= E) return;
    int j = i & 1;
    int s = src[e], d = dst[e];
    float4 v = __ldg((const float4*)&g_g2[(size_t)s * 8] + j);
    red4((float*)((float4*)&g_t2[(size_t)d * 8] + j), v);
}

// out = dinv*(t2 + g2) + b2
__global__ void k_final(const float* __restrict__ b2, float* __restrict__ out, int n) {
    int i = blockIdx.x * blockDim.x + threadIdx.x;
    if (i >= n) return;
    float d = g_dinv[i];
#pragma unroll
    for (int j = 0; j < CO; j++)
        out[(size_t)i * CO + j] =
            d * (g_t2[(size_t)i * 8 + j] + g_g2[(size_t)i * 8 + j]) + __ldg(&b2[j]);
}

// ---------- launch ----------
extern "C" void kernel_launch(void* const* d_in, const int* in_sizes, int n_in,
                              void* d_out, int out_size) {
    const float* x  = (const float*)d_in[0];
    const int*   ei = (const int*)  d_in[1];
    const float* W1 = (const float*)d_in[2];
    const float* b1 = (const float*)d_in[3];
    const float* W2 = (const float*)d_in[4];
    const float* b2 = (const float*)d_in[5];

    int n = in_sizes[0] / FIN;
    int E = in_sizes[1] / 2;
    const int* src = ei;
    const int* dst = ei + E;

    const int TB = 256;
    int gInit  = (n * HID + TB - 1) / TB;
    int gEdge  = (E + TB - 1) / TB;
    int gEdge4 = (4 * E + TB - 1) / TB;
    int gEdge2 = (2 * E + TB - 1) / TB;
    int gNode  = (n + TB - 1) / TB;
    int gXform = (n + XB - 1) / XB;

    static int smem_set = 0;
    if (!smem_set) {
        cudaFuncSetAttribute(k_xform, cudaFuncAttributeMaxDynamicSharedMemorySize, XSMEM);
        smem_set = 1;
    }

    k_init <<<gInit,  TB>>>(n);
    k_deg  <<<gEdge,  TB>>>(dst, E);
    k_dinv <<<gNode,  TB>>>(n);
    k_xform<<<gXform, XB, XSMEM>>>(x, W1, n);
    k_agg1 <<<gEdge4, TB>>>(src, dst, E);
    k_mid  <<<gNode,  TB>>>(W2, b1, n);
    k_agg2 <<<gEdge2, TB>>>(src, dst, E);
    k_final<<<gNode,  TB>>>(b2, (float*)d_out, n);
}